// round 16
// baseline (speedup 1.0000x reference)
#include <cuda_runtime.h>
#include <cstddef>
#include <cstdint>

// Problem shape (fixed by reference setup_inputs)
#define B_      16
#define T_      2048
#define D_      256
#define K_      8
#define CHUNKS  16                       // blocks per batch
#define TOK_PER_BLK (T_ / CHUNKS)        // 128 tokens per block
#define TILE_T  16
#define NTILES  (TOK_PER_BLK / TILE_T)   // 8 tiles
#define LN_EPS  1e-5f

// Dynamic smem: 3 xs tile buffers + 2 ws buffers + swred
#define XS_FLOATS   (TILE_T * D_)                 // 4096 floats per tile
#define SMEM_BYTES  (3 * XS_FLOATS * 4 + 2 * TILE_T * K_ * 8 + 64 * 4)

using ull = unsigned long long;

// Per-(batch,chunk) partial sums: [k][0..255]=sum(w*x), [k][256..511]=sum(w*x^2)
__device__ float g_part[B_][CHUNKS][K_][2 * D_];
__device__ float g_sw[B_][CHUNKS][K_];   // sum of weights per cluster

// ---------------------------------------------------------------------------
// f32x2 packed helpers (sm_10x dual fp32 pipe — PTX only)
// ---------------------------------------------------------------------------
__device__ __forceinline__ ull pk2(float lo, float hi) {
    ull r; asm("mov.b64 %0, {%1, %2};" : "=l"(r) : "f"(lo), "f"(hi)); return r;
}
__device__ __forceinline__ float2 unpk(ull v) {
    float2 r; asm("mov.b64 {%0, %1}, %2;" : "=f"(r.x), "=f"(r.y) : "l"(v)); return r;
}
__device__ __forceinline__ ull fma2(ull a, ull b, ull c) {
    ull d; asm("fma.rn.f32x2 %0, %1, %2, %3;" : "=l"(d) : "l"(a), "l"(b), "l"(c)); return d;
}
__device__ __forceinline__ ull mul2(ull a, ull b) {
    ull d; asm("mul.rn.f32x2 %0, %1, %2;" : "=l"(d) : "l"(a), "l"(b)); return d;
}

// ---------------------------------------------------------------------------
// cp.async helpers
// ---------------------------------------------------------------------------
__device__ __forceinline__ void cp_async16(unsigned int saddr, const void* gptr) {
    asm volatile("cp.async.cg.shared.global [%0], [%1], 16;" :: "r"(saddr), "l"(gptr));
}
#define CP_COMMIT() asm volatile("cp.async.commit_group;" ::: "memory")
#define CP_WAIT0()  asm volatile("cp.async.wait_group 0;"  ::: "memory")
#define CP_WAIT1()  asm volatile("cp.async.wait_group 1;"  ::: "memory")

// ---------------------------------------------------------------------------
// Main fused kernel: grid (CHUNKS, B_), 256 threads, software-pipelined:
// per iteration: sync; prefetch(t+2); weight(t+1); accumulate(t).
// ---------------------------------------------------------------------------
__global__ __launch_bounds__(256, 2)
void ldep_main_kernel(const float* __restrict__ x,
                      const float* __restrict__ centers,
                      const float* __restrict__ scale,
                      const float* __restrict__ temperature) {
    extern __shared__ float dyn[];
    float* xs0 = dyn;                    // 3 tile buffers, 16 KB each
    float* xs1 = dyn + XS_FLOATS;
    float* xs2 = dyn + 2 * XS_FLOATS;
    float2* wsb   = (float2*)(dyn + 3 * XS_FLOATS);     // [2][TILE_T][K_]
    float*  swred = (float*)(wsb + 2 * TILE_T * K_);    // [8][K_]

    const int b     = blockIdx.y;
    const int chunk = blockIdx.x;
    const int tid   = threadIdx.x;
    const int lane  = tid & 31;
    const int warp  = tid >> 5;

    // After the pass-based reduce, lane l holds full dots for g and g+4;
    // it owns cluster kk2 = g + 4*(l&1).
    const int g   = (lane >> 3) & 3;
    const int kk2 = g + 4 * (lane & 1);

    // ---- Init: centers in packed registers; per-lane selected c2/a ----
    const float tval = __ldg(temperature);
    ull c2r[K_][4];
    float c2n[K_];
#pragma unroll
    for (int k = 0; k < K_; k++) {
        const float4* cr = (const float4*)&centers[k * D_];
        float4 ca = __ldg(&cr[lane]);
        float4 cb = __ldg(&cr[lane + 32]);
        c2r[k][0] = pk2(ca.x, ca.y);
        c2r[k][1] = pk2(ca.z, ca.w);
        c2r[k][2] = pk2(cb.x, cb.y);
        c2r[k][3] = pk2(cb.z, cb.w);
        ull n = fma2(c2r[k][0], c2r[k][0],
                fma2(c2r[k][1], c2r[k][1],
                fma2(c2r[k][2], c2r[k][2],
                mul2(c2r[k][3], c2r[k][3]))));
        float2 nn = unpk(n);
        float p = nn.x + nn.y;
#pragma unroll
        for (int o = 16; o > 0; o >>= 1)
            p += __shfl_xor_sync(0xffffffffu, p, o);
        c2n[k] = p;
    }
    float c2sel = c2n[0];
#pragma unroll
    for (int j = 1; j < K_; j++) c2sel = (kk2 == j) ? c2n[j] : c2sel;
    float asel = tval * __ldg(&scale[0]);
#pragma unroll
    for (int j = 1; j < K_; j++) {
        float a = tval * __ldg(&scale[j]);
        asel = (kk2 == j) ? a : asel;
    }

    // ---- Persistent accumulators ----
    const int p = tid & 127;      // dim pair -> dims (2p, 2p+1)
    const int h = tid >> 7;       // cluster half -> clusters 4h..4h+3
    ull acc_wx[4], acc_wx2[4];
#pragma unroll
    for (int j = 0; j < 4; j++) { acc_wx[j] = 0ull; acc_wx2[j] = 0ull; }
    float acc_w = 0.0f;

    const float* xb = x + ((size_t)b * T_ + (size_t)chunk * TOK_PER_BLK) * D_;

    // ---- Weight phase (lambda): compute softmax weights for one tile ----
    auto weight_phase = [&](const float* xt, float2* wd) {
#pragma unroll
        for (int s = 0; s < 2; ++s) {
            const int tok = warp + 8 * s;
            const float4* xr = (const float4*)(xt + tok * D_);
            float4 a  = xr[lane];
            float4 b4 = xr[lane + 32];
            ull xA0 = pk2(a.x, a.y),   xA1 = pk2(a.z, a.w);
            ull xB0 = pk2(b4.x, b4.y), xB1 = pk2(b4.z, b4.w);

            float red[9];
            {
                ull x2p = fma2(xA0, xA0, fma2(xA1, xA1,
                          fma2(xB0, xB0, mul2(xB1, xB1))));
                float2 u = unpk(x2p);
                red[8] = u.x + u.y;
            }
#pragma unroll
            for (int k = 0; k < K_; k++) {
                ull d = fma2(c2r[k][0], xA0, fma2(c2r[k][1], xA1,
                        fma2(c2r[k][2], xB0, mul2(c2r[k][3], xB1))));
                float2 u = unpk(d);
                red[k] = u.x + u.y;
            }
            // Stage 1: class sums (class = lane mod 8)
#pragma unroll
            for (int j = 0; j < 9; j++)
                red[j] += __shfl_xor_sync(0xffffffffu, red[j], 16);
#pragma unroll
            for (int j = 0; j < 9; j++)
                red[j] += __shfl_xor_sync(0xffffffffu, red[j], 8);
            // Stage 2: three values per lane, offsets {1,2,4}
            float vA = red[0];
#pragma unroll
            for (int j = 1; j < 4; j++) vA = (g == j) ? red[j] : vA;
            float vB = red[4];
#pragma unroll
            for (int j = 1; j < 4; j++) vB = (g == j) ? red[4 + j] : vB;
            float vC = red[8];
#pragma unroll
            for (int o = 1; o <= 4; o <<= 1) {
                vA += __shfl_xor_sync(0xffffffffu, vA, o);
                vB += __shfl_xor_sync(0xffffffffu, vB, o);
                vC += __shfl_xor_sync(0xffffffffu, vC, o);
            }
            // One exp per lane for cluster kk2
            float dot  = (lane & 1) ? vB : vA;
            float dist = vC - 2.0f * dot + c2sel;
            float lg   = -asel * dist;
            float mx = lg;
            mx = fmaxf(mx, __shfl_xor_sync(0xffffffffu, mx, 1));
            mx = fmaxf(mx, __shfl_xor_sync(0xffffffffu, mx, 8));
            mx = fmaxf(mx, __shfl_xor_sync(0xffffffffu, mx, 16));
            float e = __expf(lg - mx);
            float sm = e;
            sm += __shfl_xor_sync(0xffffffffu, sm, 1);
            sm += __shfl_xor_sync(0xffffffffu, sm, 8);
            sm += __shfl_xor_sync(0xffffffffu, sm, 16);
            float wv = __fdividef(e, sm);
            if ((lane & 6) == 0) {
                wd[tok * K_ + kk2] = make_float2(wv, wv);
                acc_w += wv;
            }
        }
    };

    // ---- Accumulate phase (lambda): packed f32x2 ----
    auto accum_phase = [&](const float* xt, const float2* wd) {
#pragma unroll 4
        for (int tok = 0; tok < TILE_T; ++tok) {
            ull xv = *(const ull*)(xt + tok * D_ + 2 * p);
            ull xq = mul2(xv, xv);
            const ulonglong2* wr = (const ulonglong2*)(wd + tok * K_ + 4 * h);
            ulonglong2 wA = wr[0];
            ulonglong2 wB = wr[1];
            acc_wx[0]  = fma2(wA.x, xv, acc_wx[0]);
            acc_wx2[0] = fma2(wA.x, xq, acc_wx2[0]);
            acc_wx[1]  = fma2(wA.y, xv, acc_wx[1]);
            acc_wx2[1] = fma2(wA.y, xq, acc_wx2[1]);
            acc_wx[2]  = fma2(wB.x, xv, acc_wx[2]);
            acc_wx2[2] = fma2(wB.x, xq, acc_wx2[2]);
            acc_wx[3]  = fma2(wB.y, xv, acc_wx[3]);
            acc_wx2[3] = fma2(wB.y, xq, acc_wx2[3]);
        }
    };

    auto prefetch = [&](int t, float* buf) {
        const float4* src = (const float4*)(xb + (size_t)t * TILE_T * D_);
        unsigned int dst = (unsigned int)__cvta_generic_to_shared(buf);
#pragma unroll
        for (int i = 0; i < 4; i++)
            cp_async16(dst + (unsigned int)(tid + 256 * i) * 16u, src + tid + 256 * i);
        CP_COMMIT();
    };

    // ---- Prologue: tiles 0 and 1 in flight; weights for tile 0 ----
    prefetch(0, xs0);            // G0
    prefetch(1, xs1);            // G1
    CP_WAIT1();                  // G0 complete (G1 may be pending)
    __syncthreads();             // tile 0 visible to all
    weight_phase(xs0, wsb);      // ws[0]

    float* cur = xs0;
    float* nxt = xs1;
    float* fut = xs2;

#pragma unroll 1
    for (int t = 0; t < NTILES; ++t) {
        CP_WAIT0();              // tile t+1 complete (issued one iteration ago)
        __syncthreads();         // ws[t] + tile t+1 visible; fut free for reuse
        if (t + 2 < NTILES) prefetch(t + 2, fut);
        if (t + 1 < NTILES) weight_phase(nxt, wsb + (size_t)((t + 1) & 1) * TILE_T * K_);
        accum_phase(cur, wsb + (size_t)(t & 1) * TILE_T * K_);
        float* tmp = cur; cur = nxt; nxt = fut; fut = tmp;
    }

    // ---- Flush per-block partials (disjoint slots, no atomics) ----
#pragma unroll
    for (int j = 0; j < 4; j++) {
        const int k = 4 * h + j;
        float* base = &g_part[b][chunk][k][0];
        float2 vx = unpk(acc_wx[j]);
        float2 vq = unpk(acc_wx2[j]);
        *(float2*)(base + 2 * p)      = vx;
        *(float2*)(base + D_ + 2 * p) = vq;
    }
    if ((lane & 6) == 0) swred[warp * K_ + kk2] = acc_w;
    __syncthreads();
    if (tid < K_) {
        float s = 0.0f;
#pragma unroll
        for (int w = 0; w < 8; w++) s += swred[w * K_ + tid];
        g_sw[b][chunk][tid] = s;
    }
}

// ---------------------------------------------------------------------------
// Finalize: high-MLP chunk reduction + LayerNorm(512)
//   grid (K_, B_), 256 threads: thread = (dim-group d = tid&63, quarter q = tid>>6)
// ---------------------------------------------------------------------------
__device__ __forceinline__ float4 add4(float4 a, float4 b) {
    return make_float4(a.x + b.x, a.y + b.y, a.z + b.z, a.w + b.w);
}

__global__ __launch_bounds__(256)
void ldep_finalize_kernel(const float* __restrict__ centers,
                          float* __restrict__ out) {
    __shared__ float4 redx[4][64];
    __shared__ float4 redq[4][64];
    __shared__ float  s_sw[16];
    __shared__ float  r1s[2], r2s[2];

    const int b   = blockIdx.y;
    const int k   = blockIdx.x;
    const int tid = threadIdx.x;
    const int d   = tid & 63;   // dim group: dims 4d..4d+3
    const int q   = tid >> 6;   // chunk quarter: chunks 4q..4q+3

    float4 sx = make_float4(0.f, 0.f, 0.f, 0.f);
    float4 sq = make_float4(0.f, 0.f, 0.f, 0.f);
#pragma unroll
    for (int j = 0; j < 4; j++) {
        const float4* px = (const float4*)&g_part[b][4 * q + j][k][0];
        sx = add4(sx, px[d]);        // swx  dims 4d..4d+3
        sq = add4(sq, px[64 + d]);   // swx2 dims 4d..4d+3
    }
    redx[q][d] = sx;
    redq[q][d] = sq;
    if (tid < 16) s_sw[tid] = g_sw[b][tid][k];
    __syncthreads();

    float4 mean4 = make_float4(0.f, 0.f, 0.f, 0.f);
    float4 var4  = make_float4(0.f, 0.f, 0.f, 0.f);
    if (tid < 64) {
        float4 ax = add4(add4(redx[0][tid], redx[1][tid]),
                         add4(redx[2][tid], redx[3][tid]));
        float4 aq = add4(add4(redq[0][tid], redq[1][tid]),
                         add4(redq[2][tid], redq[3][tid]));
        float sw = 0.0f;
#pragma unroll
        for (int j = 0; j < 16; j++) sw += s_sw[j];
        float4 cc = __ldg((const float4*)&centers[k * D_] + tid);

        // Same algebraic decomposition as the reference
        mean4.x = ax.x - cc.x * sw;  mean4.y = ax.y - cc.y * sw;
        mean4.z = ax.z - cc.z * sw;  mean4.w = ax.w - cc.w * sw;
        float4 E;
        E.x = aq.x - 2.0f * cc.x * ax.x + cc.x * cc.x * sw;
        E.y = aq.y - 2.0f * cc.y * ax.y + cc.y * cc.y * sw;
        E.z = aq.z - 2.0f * cc.z * ax.z + cc.z * cc.z * sw;
        E.w = aq.w - 2.0f * cc.w * ax.w + cc.w * cc.w * sw;
        var4.x = E.x - mean4.x * mean4.x;
        var4.y = E.y - mean4.y * mean4.y;
        var4.z = E.z - mean4.z * mean4.z;
        var4.w = E.w - mean4.w * mean4.w;

        float s1 = mean4.x + mean4.y + mean4.z + mean4.w
                 + var4.x  + var4.y  + var4.z  + var4.w;
        float s2 = mean4.x * mean4.x + mean4.y * mean4.y
                 + mean4.z * mean4.z + mean4.w * mean4.w
                 + var4.x * var4.x + var4.y * var4.y
                 + var4.z * var4.z + var4.w * var4.w;
#pragma unroll
        for (int o = 16; o > 0; o >>= 1) {
            s1 += __shfl_xor_sync(0xffffffffu, s1, o);
            s2 += __shfl_xor_sync(0xffffffffu, s2, o);
        }
        if ((tid & 31) == 0) { r1s[tid >> 5] = s1; r2s[tid >> 5] = s2; }
    }
    __syncthreads();
    if (tid < 64) {
        const float S1 = r1s[0] + r1s[1];
        const float S2 = r2s[0] + r2s[1];
        const float mu  = S1 * (1.0f / 512.0f);
        const float v   = S2 * (1.0f / 512.0f) - mu * mu;
        const float inv = rsqrtf(v + LN_EPS);

        float4* o = (float4*)(out + ((size_t)b * K_ + k) * (2 * D_));
        o[tid] = make_float4((mean4.x - mu) * inv, (mean4.y - mu) * inv,
                             (mean4.z - mu) * inv, (mean4.w - mu) * inv);
        o[64 + tid] = make_float4((var4.x - mu) * inv, (var4.y - mu) * inv,
                                  (var4.z - mu) * inv, (var4.w - mu) * inv);
    }
}

// ---------------------------------------------------------------------------
// Launch: inputs per metadata order: x, centers, scale, temperature
// ---------------------------------------------------------------------------
extern "C" void kernel_launch(void* const* d_in, const int* in_sizes, int n_in,
                              void* d_out, int out_size) {
    const float* x           = (const float*)d_in[0];
    const float* centers     = (const float*)d_in[1];
    const float* scale       = (const float*)d_in[2];
    const float* temperature = (const float*)d_in[3];
    float* out               = (float*)d_out;

    cudaFuncSetAttribute(ldep_main_kernel,
                         cudaFuncAttributeMaxDynamicSharedMemorySize, SMEM_BYTES);
    ldep_main_kernel<<<dim3(CHUNKS, B_), 256, SMEM_BYTES>>>(x, centers, scale, temperature);
    ldep_finalize_kernel<<<dim3(K_, B_), 256>>>(centers, out);
}

// round 17
// speedup vs baseline: 1.4912x; 1.4912x over previous
#include <cuda_runtime.h>
#include <cstddef>
#include <cstdint>

// Problem shape (fixed by reference setup_inputs)
#define B_      16
#define T_      2048
#define D_      256
#define K_      8
#define CHUNKS  16                       // blocks per batch
#define TOK_PER_BLK (T_ / CHUNKS)        // 128 tokens per block
#define TILE_T  16
#define NTILES  (TOK_PER_BLK / TILE_T)   // 8 tiles
#define LN_EPS  1e-5f

using ull = unsigned long long;

// Per-(batch,chunk) partial sums: [k][0..255]=sum(w*x), [k][256..511]=sum(w*x^2)
__device__ float g_part[B_][CHUNKS][K_][2 * D_];
__device__ float g_sw[B_][CHUNKS][K_];   // sum of weights per cluster

// ---------------------------------------------------------------------------
// f32x2 packed helpers (sm_10x dual fp32 pipe — PTX only)
// ---------------------------------------------------------------------------
__device__ __forceinline__ ull pk2(float lo, float hi) {
    ull r; asm("mov.b64 %0, {%1, %2};" : "=l"(r) : "f"(lo), "f"(hi)); return r;
}
__device__ __forceinline__ float2 unpk(ull v) {
    float2 r; asm("mov.b64 {%0, %1}, %2;" : "=f"(r.x), "=f"(r.y) : "l"(v)); return r;
}
__device__ __forceinline__ ull fma2(ull a, ull b, ull c) {
    ull d; asm("fma.rn.f32x2 %0, %1, %2, %3;" : "=l"(d) : "l"(a), "l"(b), "l"(c)); return d;
}
__device__ __forceinline__ ull mul2(ull a, ull b) {
    ull d; asm("mul.rn.f32x2 %0, %1, %2;" : "=l"(d) : "l"(a), "l"(b)); return d;
}

// ---------------------------------------------------------------------------
// cp.async helpers
// ---------------------------------------------------------------------------
__device__ __forceinline__ void cp_async16(unsigned int saddr, const void* gptr) {
    asm volatile("cp.async.cg.shared.global [%0], [%1], 16;" :: "r"(saddr), "l"(gptr));
}
#define CP_COMMIT() asm volatile("cp.async.commit_group;" ::: "memory")
#define CP_WAIT0()  asm volatile("cp.async.wait_group 0;"  ::: "memory")

// ---------------------------------------------------------------------------
// Main fused kernel: grid (CHUNKS, B_), 256 threads (R6 structure)
// ---------------------------------------------------------------------------
__global__ __launch_bounds__(256, 2)
void ldep_main_kernel(const float* __restrict__ x,
                      const float* __restrict__ centers,
                      const float* __restrict__ scale,
                      const float* __restrict__ temperature) {
    __shared__ float  xs[2][TILE_T][D_];                // 2 x 16 KB tile buffers
    __shared__ __align__(16) float2 ws2[TILE_T][K_];    // weights duplicated (w,w)
    __shared__ float swred[8][K_];

    const int b     = blockIdx.y;
    const int chunk = blockIdx.x;
    const int tid   = threadIdx.x;
    const int lane  = tid & 31;
    const int warp  = tid >> 5;

    // After the halving butterfly, lane l holds the full dot for cluster
    //   kk = 4*b2 + 2*b3 + b4   (b2=(l>>2)&1, b3=(l>>3)&1, b4=(l>>4)&1)
    const int q2 = (lane >> 2) & 1;
    const int q3 = (lane >> 3) & 1;
    const int q4 = (lane >> 4) & 1;
    const int kk = 4 * q2 + 2 * q3 + q4;

    // ---- Init: centers in packed registers; per-lane selected c2/a ----
    const float tval = __ldg(temperature);
    ull c2r[K_][4];
    float c2n[K_];
#pragma unroll
    for (int k = 0; k < K_; k++) {
        const float4* cr = (const float4*)&centers[k * D_];
        float4 ca = __ldg(&cr[lane]);
        float4 cb = __ldg(&cr[lane + 32]);
        c2r[k][0] = pk2(ca.x, ca.y);
        c2r[k][1] = pk2(ca.z, ca.w);
        c2r[k][2] = pk2(cb.x, cb.y);
        c2r[k][3] = pk2(cb.z, cb.w);
        ull n = fma2(c2r[k][0], c2r[k][0],
                fma2(c2r[k][1], c2r[k][1],
                fma2(c2r[k][2], c2r[k][2],
                mul2(c2r[k][3], c2r[k][3]))));
        float2 nn = unpk(n);
        float p = nn.x + nn.y;
#pragma unroll
        for (int o = 16; o > 0; o >>= 1)
            p += __shfl_xor_sync(0xffffffffu, p, o);
        c2n[k] = p;
    }
    float c2sel = c2n[0];
#pragma unroll
    for (int j = 1; j < K_; j++) c2sel = (kk == j) ? c2n[j] : c2sel;
    float asel = tval * __ldg(&scale[0]);
#pragma unroll
    for (int j = 1; j < K_; j++) {
        float a = tval * __ldg(&scale[j]);
        asel = (kk == j) ? a : asel;
    }

    // ---- Persistent accumulators ----
    const int p = tid & 127;      // dim pair -> dims (2p, 2p+1)
    const int h = tid >> 7;       // cluster half -> clusters 4h..4h+3
    ull acc_wx[4], acc_wx2[4];
#pragma unroll
    for (int j = 0; j < 4; j++) { acc_wx[j] = 0ull; acc_wx2[j] = 0ull; }
    float acc_w = 0.0f;           // at lanes (lane&3)==0: partial s_w for cluster kk

    const float* xb = x + ((size_t)b * T_ + (size_t)chunk * TOK_PER_BLK) * D_;

    // Prefetch tile 0
    {
        const float4* src = (const float4*)xb;
        unsigned int dst = (unsigned int)__cvta_generic_to_shared(&xs[0][0][0]);
#pragma unroll
        for (int i = 0; i < 4; i++)
            cp_async16(dst + (unsigned int)(tid + 256 * i) * 16u, src + tid + 256 * i);
        CP_COMMIT();
    }

    for (int t = 0; t < NTILES; ++t) {
        const int bsel = t & 1;
        CP_WAIT0();
        __syncthreads();

        // Prefetch next tile (overlaps weight+accumulate below)
        if (t + 1 < NTILES) {
            const float4* src = (const float4*)(xb + (size_t)(t + 1) * TILE_T * D_);
            unsigned int dst = (unsigned int)__cvta_generic_to_shared(&xs[(t + 1) & 1][0][0]);
#pragma unroll
            for (int i = 0; i < 4; i++)
                cp_async16(dst + (unsigned int)(tid + 256 * i) * 16u, src + tid + 256 * i);
            CP_COMMIT();
        }

        // ---- Weight phase: warp w handles tokens w, w+8 ----
#pragma unroll
        for (int s = 0; s < 2; ++s) {
            const int tok = warp + 8 * s;
            const float4* xr = (const float4*)&xs[bsel][tok][0];
            float4 a  = xr[lane];
            float4 b4v = xr[lane + 32];
            ull xA0 = pk2(a.x, a.y),    xA1 = pk2(a.z, a.w);
            ull xB0 = pk2(b4v.x, b4v.y), xB1 = pk2(b4v.z, b4v.w);

            float red[8];
            float x2p;
            {
                ull x2u = fma2(xA0, xA0, fma2(xA1, xA1,
                          fma2(xB0, xB0, mul2(xB1, xB1))));
                float2 u = unpk(x2u);
                x2p = u.x + u.y;
            }
#pragma unroll
            for (int k = 0; k < K_; k++) {
                ull d = fma2(c2r[k][0], xA0, fma2(c2r[k][1], xA1,
                        fma2(c2r[k][2], xB0, mul2(c2r[k][3], xB1))));
                float2 u = unpk(d);
                red[k] = u.x + u.y;
            }

            // Halving butterfly: 14 shfl to full 32-lane sums.
            // Round A (xor 16): pairs (0,1)(2,3)(4,5)(6,7), keep-by-b4
            float tA[4];
#pragma unroll
            for (int j = 0; j < 4; j++) {
                float keep = q4 ? red[2 * j + 1] : red[2 * j];
                float send = q4 ? red[2 * j]     : red[2 * j + 1];
                tA[j] = keep + __shfl_xor_sync(0xffffffffu, send, 16);
            }
            float tX = x2p + __shfl_xor_sync(0xffffffffu, x2p, 16);
            // Round B (xor 8): pairs (t0,t1)(t2,t3), keep-by-b3
            float uB[2];
#pragma unroll
            for (int j = 0; j < 2; j++) {
                float keep = q3 ? tA[2 * j + 1] : tA[2 * j];
                float send = q3 ? tA[2 * j]     : tA[2 * j + 1];
                uB[j] = keep + __shfl_xor_sync(0xffffffffu, send, 8);
            }
            tX += __shfl_xor_sync(0xffffffffu, tX, 8);
            // Round C (xor 4): pair (u0,u1), keep-by-b2
            float w0;
            {
                float keep = q2 ? uB[1] : uB[0];
                float send = q2 ? uB[0] : uB[1];
                w0 = keep + __shfl_xor_sync(0xffffffffu, send, 4);
            }
            tX += __shfl_xor_sync(0xffffffffu, tX, 4);
            // Rounds D,E (xor 2, xor 1): finish the lane sums
            w0 += __shfl_xor_sync(0xffffffffu, w0, 2);
            tX += __shfl_xor_sync(0xffffffffu, tX, 2);
            w0 += __shfl_xor_sync(0xffffffffu, w0, 1);
            tX += __shfl_xor_sync(0xffffffffu, tX, 1);
            // Now: w0 = dot[kk] (full), tX = x2 (full, all lanes)

            float dist = tX - 2.0f * w0 + c2sel;
            float lg   = -asel * dist;
            // softmax over the 8 clusters: k lives in lane bits {2,3,4}
            float mx = lg;
            mx = fmaxf(mx, __shfl_xor_sync(0xffffffffu, mx, 4));
            mx = fmaxf(mx, __shfl_xor_sync(0xffffffffu, mx, 8));
            mx = fmaxf(mx, __shfl_xor_sync(0xffffffffu, mx, 16));
            float e = __expf(lg - mx);
            float sm = e;
            sm += __shfl_xor_sync(0xffffffffu, sm, 4);
            sm += __shfl_xor_sync(0xffffffffu, sm, 8);
            sm += __shfl_xor_sync(0xffffffffu, sm, 16);
            float wv = __fdividef(e, sm);
            if ((lane & 3) == 0) {       // lanes 0,4,..,28 -> 8 distinct kk
                ws2[tok][kk] = make_float2(wv, wv);
                acc_w += wv;
            }
        }
        __syncthreads();

        // ---- Accumulate phase (packed f32x2) ----
#pragma unroll 4
        for (int tok = 0; tok < TILE_T; ++tok) {
            ull xv = *(const ull*)&xs[bsel][tok][2 * p];   // dims (2p, 2p+1)
            ull xq = mul2(xv, xv);
            const ulonglong2* wr = (const ulonglong2*)&ws2[tok][4 * h];
            ulonglong2 wA = wr[0];
            ulonglong2 wB = wr[1];
            acc_wx[0]  = fma2(wA.x, xv, acc_wx[0]);
            acc_wx2[0] = fma2(wA.x, xq, acc_wx2[0]);
            acc_wx[1]  = fma2(wA.y, xv, acc_wx[1]);
            acc_wx2[1] = fma2(wA.y, xq, acc_wx2[1]);
            acc_wx[2]  = fma2(wB.x, xv, acc_wx[2]);
            acc_wx2[2] = fma2(wB.x, xq, acc_wx2[2]);
            acc_wx[3]  = fma2(wB.y, xv, acc_wx[3]);
            acc_wx2[3] = fma2(wB.y, xq, acc_wx2[3]);
        }
    }

    // ---- Flush per-block partials (disjoint slots, no atomics) ----
#pragma unroll
    for (int j = 0; j < 4; j++) {
        const int k = 4 * h + j;
        float* base = &g_part[b][chunk][k][0];
        float2 vx = unpk(acc_wx[j]);
        float2 vq = unpk(acc_wx2[j]);
        *(float2*)(base + 2 * p)      = vx;
        *(float2*)(base + D_ + 2 * p) = vq;
    }
    if ((lane & 3) == 0) swred[warp][kk] = acc_w;
    __syncthreads();
    if (tid < K_) {
        float s = 0.0f;
#pragma unroll
        for (int w = 0; w < 8; w++) s += swred[w][tid];
        g_sw[b][chunk][tid] = s;
    }

    // PDL: make our writes visible, then allow the dependent grid to launch
    __threadfence();
    asm volatile("griddepcontrol.launch_dependents;" ::: "memory");
}

// ---------------------------------------------------------------------------
// Finalize: 512 threads, two chunk-halves in parallel; PDL-overlapped start
//   grid (K_, B_): d = tid&255 (dim), half = tid>>8 (chunks 8h..8h+7)
// ---------------------------------------------------------------------------
__global__ __launch_bounds__(512)
void ldep_finalize_kernel(const float* __restrict__ centers,
                          float* __restrict__ out) {
    __shared__ float sx[2][D_], sq[2][D_];
    __shared__ float s_sw;
    __shared__ float r1[8], r2[8];

    const int b    = blockIdx.y;
    const int k    = blockIdx.x;
    const int tid  = threadIdx.x;
    const int d    = tid & 255;
    const int half = tid >> 8;

    // Independent of main's output: prefetch before the dependency wait
    const float cc = __ldg(&centers[k * D_ + d]);

    asm volatile("griddepcontrol.wait;" ::: "memory");

    float swx = 0.0f, swx2 = 0.0f;
#pragma unroll
    for (int j = 0; j < 8; j++) {
        const int c = 8 * half + j;
        swx  += g_part[b][c][k][d];
        swx2 += g_part[b][c][k][D_ + d];
    }
    sx[half][d] = swx;
    sq[half][d] = swx2;

    float swp = 0.0f;
    if (tid < 16) swp = g_sw[b][tid][k];
    if (tid < 32) {
#pragma unroll
        for (int o = 8; o > 0; o >>= 1)
            swp += __shfl_xor_sync(0xffffffffu, swp, o);
        if (tid == 0) s_sw = swp;
    }
    __syncthreads();

    float mean = 0.0f, var = 0.0f;
    if (half == 0) {
        const float ax = sx[0][d] + sx[1][d];
        const float aq = sq[0][d] + sq[1][d];
        const float sw = s_sw;

        // Same algebraic decomposition as the reference
        mean = ax - cc * sw;
        const float E = aq - 2.0f * cc * ax + cc * cc * sw;
        var = E - mean * mean;

        float s1 = mean + var;
        float s2 = mean * mean + var * var;
#pragma unroll
        for (int o = 16; o > 0; o >>= 1) {
            s1 += __shfl_xor_sync(0xffffffffu, s1, o);
            s2 += __shfl_xor_sync(0xffffffffu, s2, o);
        }
        if ((tid & 31) == 0) { r1[tid >> 5] = s1; r2[tid >> 5] = s2; }
    }
    __syncthreads();
    if (half == 0) {
        float S1 = 0.0f, S2 = 0.0f;
#pragma unroll
        for (int i = 0; i < 8; i++) { S1 += r1[i]; S2 += r2[i]; }
        const float mu  = S1 * (1.0f / 512.0f);
        const float v   = S2 * (1.0f / 512.0f) - mu * mu;
        const float inv = rsqrtf(v + LN_EPS);

        float* o = out + ((size_t)b * K_ + k) * (2 * D_);
        o[d]      = (mean - mu) * inv;
        o[D_ + d] = (var  - mu) * inv;
    }
}

// ---------------------------------------------------------------------------
// Launch: inputs per metadata order: x, centers, scale, temperature
// ---------------------------------------------------------------------------
extern "C" void kernel_launch(void* const* d_in, const int* in_sizes, int n_in,
                              void* d_out, int out_size) {
    const float* x           = (const float*)d_in[0];
    const float* centers     = (const float*)d_in[1];
    const float* scale       = (const float*)d_in[2];
    const float* temperature = (const float*)d_in[3];
    float* out               = (float*)d_out;

    ldep_main_kernel<<<dim3(CHUNKS, B_), 256>>>(x, centers, scale, temperature);

    // Finalize with programmatic dependent launch (overlaps main's tail)
    cudaLaunchConfig_t cfg = {};
    cfg.gridDim  = dim3(K_, B_);
    cfg.blockDim = dim3(512);
    cfg.dynamicSmemBytes = 0;
    cfg.stream = 0;
    cudaLaunchAttribute attrs[1];
    attrs[0].id = cudaLaunchAttributeProgrammaticStreamSerialization;
    attrs[0].val.programmaticStreamSerializationAllowed = 1;
    cfg.attrs = attrs;
    cfg.numAttrs = 1;
    cudaLaunchKernelEx(&cfg, ldep_finalize_kernel, centers, out);
}